// round 13
// baseline (speedup 1.0000x reference)
#include <cuda_runtime.h>
#include <cuda_fp16.h>
#include <stdint.h>

#define N_NODES  50000
#define N_EDGES  1600000
#define IN_F     128
#define OUT_F    128
#define HEADS    4
#define HEAD_DIM 32
#define NEG_SLOPE 0.2f

#define GEMM_BM     64
#define GEMM_BLOCKS 782             // ceil(50000/64)
#define EDGE8_BLOCKS 782            // ceil(1.6M / (256 thr * 8 edges))

// ---------------- device scratch ----------------
__device__ __half2 g_h2[N_NODES * (OUT_F / 2)];  // h as half2 (12.8 MB)
__device__ float   g_as[N_NODES * HEADS];
__device__ float   g_ad[N_NODES * HEADS];
__device__ uint4   g_Wf[2048];                   // W in mma B-fragment layout (32KB)
__device__ int     g_cnt[N_NODES];
__device__ int     g_off[N_NODES + 1];
__device__ int     g_epos[N_EDGES];              // within-bucket position per edge
__device__ int     g_srcs[N_EDGES];              // src index, sorted by dst
__device__ int     g_is64;

// ---------------- dtype detect --------------------------------------------
__global__ void detect_kernel(const int* __restrict__ ei) {
    int allzero = 1;
    #pragma unroll 1
    for (int i2 = 1; i2 < 256; i2 += 2)
        if (ei[i2] != 0) { allzero = 0; break; }
    g_is64 = allzero;
}

// ---------------- W fragment packing (stream 1) ----------------------------
// g_Wf[(ks*8 + j)*32 + lane] = uint4{ b0(n=2j), b1(n=2j), b0(n=2j+1), b1(n=2j+1) }
__global__ __launch_bounds__(256) void init_kernel(const float* __restrict__ W) {
    const int L = blockIdx.x * 256 + threadIdx.x;   // 8 blocks * 256 = 2048
    const int lane = L & 31;
    const int j    = (L >> 5) & 7;
    const int ks   = L >> 8;
    const int k0   = ks * 16 + (lane & 3) * 2;

    uint4 q;
    #pragma unroll
    for (int p = 0; p < 2; p++) {
        const int col = (2 * j + p) * 8 + (lane >> 2);
        const float* wr = W + col * IN_F;
        __half2 b0 = __floats2half2_rn(wr[k0],     wr[k0 + 1]);
        __half2 b1 = __floats2half2_rn(wr[k0 + 8], wr[k0 + 9]);
        if (p == 0) { q.x = *(const unsigned*)&b0; q.y = *(const unsigned*)&b1; }
        else        { q.z = *(const unsigned*)&b0; q.w = *(const unsigned*)&b1; }
    }
    g_Wf[L] = q;
}

// ---------------- histogram + within-bucket positions (8 edges/thread) ----
__global__ __launch_bounds__(256) void hist_kernel(const int* __restrict__ ei32) {
    const int e8 = (blockIdx.x * blockDim.x + threadIdx.x) * 8;
    if (e8 >= N_EDGES) return;
    int d[8];
    if (g_is64) {
        const longlong2* p = (const longlong2*)((const long long*)ei32 + N_EDGES + e8);
        longlong2 v0 = p[0], v1 = p[1], v2 = p[2], v3 = p[3];
        d[0] = (int)v0.x; d[1] = (int)v0.y; d[2] = (int)v1.x; d[3] = (int)v1.y;
        d[4] = (int)v2.x; d[5] = (int)v2.y; d[6] = (int)v3.x; d[7] = (int)v3.y;
    } else {
        int4 v0 = *(const int4*)(ei32 + N_EDGES + e8);
        int4 v1 = *(const int4*)(ei32 + N_EDGES + e8 + 4);
        d[0] = v0.x; d[1] = v0.y; d[2] = v0.z; d[3] = v0.w;
        d[4] = v1.x; d[5] = v1.y; d[6] = v1.z; d[7] = v1.w;
    }
    int pos[8];
    #pragma unroll
    for (int p = 0; p < 8; p++)
        pos[p] = atomicAdd(&g_cnt[d[p]], 1);
    *(int4*)&g_epos[e8]     = make_int4(pos[0], pos[1], pos[2], pos[3]);
    *(int4*)&g_epos[e8 + 4] = make_int4(pos[4], pos[5], pos[6], pos[7]);
}

// ---------------- single-CTA scan, coalesced 1024-rounds ------------------
__global__ __launch_bounds__(1024) void scan_kernel() {
    __shared__ int wtot[32];
    const int t = threadIdx.x;
    const int lane = t & 31, wid = t >> 5;
    const unsigned m = 0xffffffffu;
    int base = 0;

    #pragma unroll 1
    for (int i = 0; i < (N_NODES + 1023) / 1024; i++) {
        const int idx = i * 1024 + t;
        const int v = (idx < N_NODES) ? g_cnt[idx] : 0;
        int incl = v;
        #pragma unroll
        for (int off = 1; off < 32; off <<= 1) {
            int u = __shfl_up_sync(m, incl, off);
            if (lane >= off) incl += u;
        }
        if (lane == 31) wtot[wid] = incl;
        __syncthreads();
        if (wid == 0) {
            int w2 = wtot[lane];
            #pragma unroll
            for (int off = 1; off < 32; off <<= 1) {
                int u = __shfl_up_sync(m, w2, off);
                if (lane >= off) w2 += u;
            }
            wtot[lane] = w2;
        }
        __syncthreads();
        const int excl = incl - v + (wid ? wtot[wid - 1] : 0) + base;
        if (idx < N_NODES) g_off[idx] = excl;
        base += wtot[31];
        __syncthreads();
    }
    if (t == 0) g_off[N_NODES] = base;
}

// ---------------- scatter: atomic-free, 8 edges/thread --------------------
__global__ __launch_bounds__(256) void scatter_kernel(const int* __restrict__ ei32) {
    const int e8 = (blockIdx.x * blockDim.x + threadIdx.x) * 8;
    if (e8 >= N_EDGES) return;
    int s[8], d[8];
    if (g_is64) {
        const long long* ei = (const long long*)ei32;
        const longlong2* sp = (const longlong2*)(ei + e8);
        const longlong2* dp = (const longlong2*)(ei + N_EDGES + e8);
        #pragma unroll
        for (int q = 0; q < 4; q++) {
            longlong2 sv = sp[q], dv = dp[q];
            s[2*q] = (int)sv.x; s[2*q+1] = (int)sv.y;
            d[2*q] = (int)dv.x; d[2*q+1] = (int)dv.y;
        }
    } else {
        int4 sv0 = *(const int4*)(ei32 + e8);
        int4 sv1 = *(const int4*)(ei32 + e8 + 4);
        int4 dv0 = *(const int4*)(ei32 + N_EDGES + e8);
        int4 dv1 = *(const int4*)(ei32 + N_EDGES + e8 + 4);
        s[0]=sv0.x; s[1]=sv0.y; s[2]=sv0.z; s[3]=sv0.w;
        s[4]=sv1.x; s[5]=sv1.y; s[6]=sv1.z; s[7]=sv1.w;
        d[0]=dv0.x; d[1]=dv0.y; d[2]=dv0.z; d[3]=dv0.w;
        d[4]=dv1.x; d[5]=dv1.y; d[6]=dv1.z; d[7]=dv1.w;
    }
    int4 p0 = *(const int4*)&g_epos[e8];
    int4 p1 = *(const int4*)&g_epos[e8 + 4];
    int pos[8] = {p0.x, p0.y, p0.z, p0.w, p1.x, p1.y, p1.z, p1.w};
    int off[8];
    #pragma unroll
    for (int p = 0; p < 8; p++) off[p] = g_off[d[p]];
    #pragma unroll
    for (int p = 0; p < 8; p++) g_srcs[off[p] + pos[p]] = s[p];
}

// ---------------- tensor-core GEMM: h = x@W^T + alpha ----------------------
__device__ __forceinline__ void mma16816(
    float* c, unsigned a0, unsigned a1, unsigned a2, unsigned a3,
    unsigned b0, unsigned b1)
{
    asm volatile(
        "mma.sync.aligned.m16n8k16.row.col.f32.f16.f16.f32 "
        "{%0,%1,%2,%3}, {%4,%5,%6,%7}, {%8,%9}, {%0,%1,%2,%3};"
        : "+f"(c[0]), "+f"(c[1]), "+f"(c[2]), "+f"(c[3])
        : "r"(a0), "r"(a1), "r"(a2), "r"(a3), "r"(b0), "r"(b1));
}

__global__ __launch_bounds__(128) void gemm_kernel(
    const float* __restrict__ x,
    const float* __restrict__ a)
{
    __shared__ __half xh[GEMM_BM][IN_F + 8];

    const int t    = threadIdx.x;
    const int lane = t & 31;
    const int w    = t >> 5;
    const int rowbase = blockIdx.x * GEMM_BM;

    for (int f4 = t; f4 < GEMM_BM * 32; f4 += 128) {
        const int row = f4 >> 5, c4 = f4 & 31;
        const int grow = rowbase + row;
        float4 v = make_float4(0.f, 0.f, 0.f, 0.f);
        if (grow < N_NODES) v = *(const float4*)(x + (size_t)grow * IN_F + c4 * 4);
        __half2 h0 = __floats2half2_rn(v.x, v.y);
        __half2 h1 = __floats2half2_rn(v.z, v.w);
        uint2 u;
        u.x = *(const unsigned*)&h0;
        u.y = *(const unsigned*)&h1;
        *(uint2*)&xh[row][c4 * 4] = u;
    }
    __syncthreads();

    float acc[16][4];
    #pragma unroll
    for (int n = 0; n < 16; n++)
        #pragma unroll
        for (int q = 0; q < 4; q++) acc[n][q] = 0.f;

    const int sr = w * 16 + (lane >> 2);
    const int cc = (lane & 3) * 2;

    #pragma unroll
    for (int ks = 0; ks < 8; ks++) {
        const int kb = ks * 16;
        const unsigned a0 = *(const unsigned*)&xh[sr][kb + cc];
        const unsigned a1 = *(const unsigned*)&xh[sr + 8][kb + cc];
        const unsigned a2 = *(const unsigned*)&xh[sr][kb + cc + 8];
        const unsigned a3 = *(const unsigned*)&xh[sr + 8][kb + cc + 8];
        #pragma unroll
        for (int j = 0; j < 8; j++) {
            const uint4 q = g_Wf[(ks * 8 + j) * 32 + lane];
            mma16816(acc[2 * j],     a0, a1, a2, a3, q.x, q.y);
            mma16816(acc[2 * j + 1], a0, a1, a2, a3, q.z, q.w);
        }
    }

    const int cq = lane & 3;
    const unsigned msk = 0xffffffffu;

    #pragma unroll
    for (int rh = 0; rh < 2; rh++) {
        const int row = rowbase + w * 16 + (lane >> 2) + rh * 8;
        const bool valid = (row < N_NODES);
        float ps[4] = {0.f, 0.f, 0.f, 0.f};
        float pd[4] = {0.f, 0.f, 0.f, 0.f};

        #pragma unroll
        for (int n = 0; n < 16; n++) {
            const float c0 = acc[n][rh * 2];
            const float c1 = acc[n][rh * 2 + 1];
            if (valid) {
                __half2 hp = __floats2half2_rn(c0, c1);
                ((unsigned*)g_h2)[(size_t)row * 64 + n * 4 + cq] = *(const unsigned*)&hp;
            }
            const int head = n >> 2;
            const int wc   = (n & 3) * 8 + cq * 2;
            const float2 asv = *(const float2*)&a[head * 64 + wc];
            const float2 adv = *(const float2*)&a[head * 64 + 32 + wc];
            ps[head] += c0 * asv.x + c1 * asv.y;
            pd[head] += c0 * adv.x + c1 * adv.y;
        }
        #pragma unroll
        for (int h = 0; h < 4; h++) {
            ps[h] += __shfl_xor_sync(msk, ps[h], 1);
            ps[h] += __shfl_xor_sync(msk, ps[h], 2);
            pd[h] += __shfl_xor_sync(msk, pd[h], 1);
            pd[h] += __shfl_xor_sync(msk, pd[h], 2);
        }
        if (valid) {
            g_as[row * HEADS + cq] = ps[cq];
            g_ad[row * HEADS + cq] = pd[cq];
        }
    }
}

// ---------------- gather: warp per node, half-warp per edge ---------------
__device__ __forceinline__ float leaky(float v) {
    return (v > 0.f) ? v : NEG_SLOPE * v;
}

__global__ __launch_bounds__(256) void gather_kernel(float* __restrict__ out) {
    const int n = blockIdx.x * 8 + (threadIdx.x >> 5);
    if (n >= N_NODES) return;
    const int lane = threadIdx.x & 31;
    const int hw = lane >> 4;
    const int sl = lane & 15;
    const int h  = sl >> 2;
    const float myad = g_ad[n * HEADS + h];

    float acc[8];
    #pragma unroll
    for (int j = 0; j < 8; j++) acc[j] = 0.f;

    const int start = g_off[n];
    const int end   = g_off[n + 1];
    int e = start;

    #pragma unroll 1
    for (; e + 8 <= end; e += 8) {
        int   si[4];
        uint4 u[4];
        float att[4];
        #pragma unroll
        for (int p = 0; p < 4; p++) si[p] = g_srcs[e + 2 * p + hw];
        #pragma unroll
        for (int p = 0; p < 4; p++) u[p] = *(const uint4*)&g_h2[(size_t)si[p] * 64 + sl * 4];
        #pragma unroll
        for (int p = 0; p < 4; p++) att[p] = leaky(g_as[si[p] * HEADS + h] + myad);
        #pragma unroll
        for (int p = 0; p < 4; p++) {
            float2 f;
            f = __half22float2(*(const __half2*)&u[p].x);
            acc[0] = fmaf(att[p], f.x, acc[0]); acc[1] = fmaf(att[p], f.y, acc[1]);
            f = __half22float2(*(const __half2*)&u[p].y);
            acc[2] = fmaf(att[p], f.x, acc[2]); acc[3] = fmaf(att[p], f.y, acc[3]);
            f = __half22float2(*(const __half2*)&u[p].z);
            acc[4] = fmaf(att[p], f.x, acc[4]); acc[5] = fmaf(att[p], f.y, acc[5]);
            f = __half22float2(*(const __half2*)&u[p].w);
            acc[6] = fmaf(att[p], f.x, acc[6]); acc[7] = fmaf(att[p], f.y, acc[7]);
        }
    }
    #pragma unroll 1
    for (; e < end; e += 2) {
        if (e + hw < end) {
            const int s = g_srcs[e + hw];
            const float att = leaky(g_as[s * HEADS + h] + myad);
            const uint4 u = *(const uint4*)&g_h2[(size_t)s * 64 + sl * 4];
            float2 f;
            f = __half22float2(*(const __half2*)&u.x);
            acc[0] = fmaf(att, f.x, acc[0]); acc[1] = fmaf(att, f.y, acc[1]);
            f = __half22float2(*(const __half2*)&u.y);
            acc[2] = fmaf(att, f.x, acc[2]); acc[3] = fmaf(att, f.y, acc[3]);
            f = __half22float2(*(const __half2*)&u.z);
            acc[4] = fmaf(att, f.x, acc[4]); acc[5] = fmaf(att, f.y, acc[5]);
            f = __half22float2(*(const __half2*)&u.w);
            acc[6] = fmaf(att, f.x, acc[6]); acc[7] = fmaf(att, f.y, acc[7]);
        }
    }

    const unsigned msk = 0xffffffffu;
    #pragma unroll
    for (int j = 0; j < 8; j++)
        acc[j] += __shfl_xor_sync(msk, acc[j], 16);

    float* op = out + (size_t)n * OUT_F + sl * 8;
    if (hw == 0)
        *(float4*)op = make_float4(acc[0], acc[1], acc[2], acc[3]);
    else
        *(float4*)(op + 4) = make_float4(acc[4], acc[5], acc[6], acc[7]);
}

// ---------------- launch: fork-join graph ---------------------------------
extern "C" void kernel_launch(void* const* d_in, const int* in_sizes, int n_in,
                              void* d_out, int out_size) {
    const float* x  = (const float*)d_in[0];
    const int*   ei = (const int*)d_in[1];
    const float* W  = (const float*)d_in[2];
    const float* a  = (const float*)d_in[3];
    float* out = (float*)d_out;

    void* cntp = nullptr;
    cudaGetSymbolAddress(&cntp, g_cnt);

    cudaStream_t s1;
    cudaStreamCreate(&s1);
    cudaEvent_t evFork, evJoin;
    cudaEventCreateWithFlags(&evFork, cudaEventDisableTiming);
    cudaEventCreateWithFlags(&evJoin, cudaEventDisableTiming);

    // fork: s1 runs the GEMM chain (independent of edge list)
    cudaEventRecord(evFork, 0);
    cudaStreamWaitEvent(s1, evFork, 0);
    init_kernel<<<8, 256, 0, s1>>>(W);
    gemm_kernel<<<GEMM_BLOCKS, 128, 0, s1>>>(x, a);
    cudaEventRecord(evJoin, s1);

    // legacy stream: CSR construction chain
    detect_kernel<<<1, 1>>>(ei);
    cudaMemsetAsync(cntp, 0, N_NODES * sizeof(int));
    hist_kernel<<<EDGE8_BLOCKS, 256>>>(ei);
    scan_kernel<<<1, 1024>>>();
    scatter_kernel<<<EDGE8_BLOCKS, 256>>>(ei);

    // join, then gather consumes both chains
    cudaStreamWaitEvent(0, evJoin, 0);
    gather_kernel<<<(N_NODES + 7) / 8, 256>>>(out);

    cudaEventDestroy(evFork);
    cudaEventDestroy(evJoin);
    cudaStreamDestroy(s1);
}

// round 14
// speedup vs baseline: 1.2679x; 1.2679x over previous
#include <cuda_runtime.h>
#include <cuda_fp16.h>
#include <stdint.h>

#define N_NODES  50000
#define N_EDGES  1600000
#define IN_F     128
#define OUT_F    128
#define HEADS    4
#define HEAD_DIM 32
#define NEG_SLOPE 0.2f

#define GEMM_BM      64
#define GEMM_BLOCKS  782            // ceil(50000/64)
#define SCAT_BLOCKS  1563           // ceil(1.6M / (128 thr * 8 edges))
#define HIST_BLOCKS  1563           // ceil(1.6M / (256 thr * 4 edges))

// ---------------- device scratch ----------------
__device__ __half2 g_h2[N_NODES * (OUT_F / 2)];  // h as half2 (12.8 MB)
__device__ float   g_as[N_NODES * HEADS];
__device__ float   g_ad[N_NODES * HEADS];
__device__ uint4   g_Wf[2048];                   // W in mma B-fragment layout (32KB)
__device__ int     g_cnt[N_NODES];
__device__ int     g_off[N_NODES + 4];
__device__ int     g_epos[N_EDGES];              // within-bucket position per edge
__device__ int     g_srcs[N_EDGES];              // src index, sorted by dst
__device__ int     g_is64;

// ---------------- dtype detect --------------------------------------------
__global__ void detect_kernel(const int* __restrict__ ei) {
    int allzero = 1;
    #pragma unroll 1
    for (int i2 = 1; i2 < 256; i2 += 2)
        if (ei[i2] != 0) { allzero = 0; break; }
    g_is64 = allzero;
}

// ---------------- W fragment packing ---------------------------------------
// g_Wf[(ks*8 + j)*32 + lane] = uint4{ b0(n=2j), b1(n=2j), b0(n=2j+1), b1(n=2j+1) }
__global__ __launch_bounds__(256) void init_kernel(const float* __restrict__ W) {
    const int L = blockIdx.x * 256 + threadIdx.x;   // 8 blocks * 256 = 2048
    const int lane = L & 31;
    const int j    = (L >> 5) & 7;
    const int ks   = L >> 8;
    const int k0   = ks * 16 + (lane & 3) * 2;

    uint4 q;
    #pragma unroll
    for (int p = 0; p < 2; p++) {
        const int col = (2 * j + p) * 8 + (lane >> 2);
        const float* wr = W + col * IN_F;
        __half2 b0 = __floats2half2_rn(wr[k0],     wr[k0 + 1]);
        __half2 b1 = __floats2half2_rn(wr[k0 + 8], wr[k0 + 9]);
        if (p == 0) { q.x = *(const unsigned*)&b0; q.y = *(const unsigned*)&b1; }
        else        { q.z = *(const unsigned*)&b0; q.w = *(const unsigned*)&b1; }
    }
    g_Wf[L] = q;
}

// ---------------- histogram + within-bucket positions (4 edges/thread) ----
__global__ __launch_bounds__(256) void hist_kernel(const int* __restrict__ ei32) {
    const int e4 = (blockIdx.x * blockDim.x + threadIdx.x) * 4;
    if (e4 >= N_EDGES) return;
    int d0, d1, d2, d3;
    if (g_is64) {
        const longlong2* p = (const longlong2*)((const long long*)ei32 + N_EDGES + e4);
        longlong2 a = p[0], b = p[1];
        d0 = (int)a.x; d1 = (int)a.y; d2 = (int)b.x; d3 = (int)b.y;
    } else {
        int4 d = *(const int4*)(ei32 + N_EDGES + e4);
        d0 = d.x; d1 = d.y; d2 = d.z; d3 = d.w;
    }
    int p0 = atomicAdd(&g_cnt[d0], 1);
    int p1 = atomicAdd(&g_cnt[d1], 1);
    int p2 = atomicAdd(&g_cnt[d2], 1);
    int p3 = atomicAdd(&g_cnt[d3], 1);
    *(int4*)&g_epos[e4] = make_int4(p0, p1, p2, p3);
}

// ---------------- single-CTA scan, int4, 13 coalesced rounds --------------
__global__ __launch_bounds__(1024) void scan_kernel() {
    __shared__ int wtot[32];
    const int t = threadIdx.x;
    const int lane = t & 31, wid = t >> 5;
    const unsigned m = 0xffffffffu;
    int base = 0;

    #pragma unroll 1
    for (int i = 0; i < (N_NODES + 4095) / 4096; i++) {
        const int idx = i * 4096 + t * 4;
        int4 v = make_int4(0, 0, 0, 0);
        if (idx + 3 < N_NODES)      v = *(const int4*)&g_cnt[idx];
        else if (idx < N_NODES) {
            v.x = g_cnt[idx];
            if (idx + 1 < N_NODES) v.y = g_cnt[idx + 1];
            if (idx + 2 < N_NODES) v.z = g_cnt[idx + 2];
        }
        const int s = v.x + v.y + v.z + v.w;
        int incl = s;
        #pragma unroll
        for (int off = 1; off < 32; off <<= 1) {
            int u = __shfl_up_sync(m, incl, off);
            if (lane >= off) incl += u;
        }
        if (lane == 31) wtot[wid] = incl;
        __syncthreads();
        if (wid == 0) {
            int w2 = wtot[lane];
            #pragma unroll
            for (int off = 1; off < 32; off <<= 1) {
                int u = __shfl_up_sync(m, w2, off);
                if (lane >= off) w2 += u;
            }
            wtot[lane] = w2;
        }
        __syncthreads();
        int run = incl - s + (wid ? wtot[wid - 1] : 0) + base;
        if (idx < N_NODES) {
            int4 o;
            o.x = run;
            o.y = run + v.x;
            o.z = run + v.x + v.y;
            o.w = run + v.x + v.y + v.z;
            *(int4*)&g_off[idx] = o;            // g_off padded to N_NODES+4
        }
        base += wtot[31];
        __syncthreads();
    }
    if (t == 0) g_off[N_NODES] = base;
}

// ---------------- fused tensor-core GEMM || atomic-free scatter ------------
__device__ __forceinline__ void mma16816(
    float* c, unsigned a0, unsigned a1, unsigned a2, unsigned a3,
    unsigned b0, unsigned b1)
{
    asm volatile(
        "mma.sync.aligned.m16n8k16.row.col.f32.f16.f16.f32 "
        "{%0,%1,%2,%3}, {%4,%5,%6,%7}, {%8,%9}, {%0,%1,%2,%3};"
        : "+f"(c[0]), "+f"(c[1]), "+f"(c[2]), "+f"(c[3])
        : "r"(a0), "r"(a1), "r"(a2), "r"(a3), "r"(b0), "r"(b1));
}

__global__ __launch_bounds__(128) void gemm_scatter_kernel(
    const float* __restrict__ x,
    const int*   __restrict__ ei32,
    const float* __restrict__ a)
{
    __shared__ __half xh[GEMM_BM][IN_F + 8];

    if (blockIdx.x >= GEMM_BLOCKS) {
        // ---- scatter path: 8 edges/thread, no atomics ----
        const int e8 = (blockIdx.x - GEMM_BLOCKS) * 1024 + threadIdx.x * 8;
        if (e8 >= N_EDGES) return;
        int s[8], d[8];
        if (g_is64) {
            const long long* ei = (const long long*)ei32;
            const longlong2* sp = (const longlong2*)(ei + e8);
            const longlong2* dp = (const longlong2*)(ei + N_EDGES + e8);
            #pragma unroll
            for (int q = 0; q < 4; q++) {
                longlong2 sv = sp[q], dv = dp[q];
                s[2*q] = (int)sv.x; s[2*q+1] = (int)sv.y;
                d[2*q] = (int)dv.x; d[2*q+1] = (int)dv.y;
            }
        } else {
            int4 sv0 = *(const int4*)(ei32 + e8);
            int4 sv1 = *(const int4*)(ei32 + e8 + 4);
            int4 dv0 = *(const int4*)(ei32 + N_EDGES + e8);
            int4 dv1 = *(const int4*)(ei32 + N_EDGES + e8 + 4);
            s[0]=sv0.x; s[1]=sv0.y; s[2]=sv0.z; s[3]=sv0.w;
            s[4]=sv1.x; s[5]=sv1.y; s[6]=sv1.z; s[7]=sv1.w;
            d[0]=dv0.x; d[1]=dv0.y; d[2]=dv0.z; d[3]=dv0.w;
            d[4]=dv1.x; d[5]=dv1.y; d[6]=dv1.z; d[7]=dv1.w;
        }
        int4 p0 = *(const int4*)&g_epos[e8];
        int4 p1 = *(const int4*)&g_epos[e8 + 4];
        int pos[8] = {p0.x, p0.y, p0.z, p0.w, p1.x, p1.y, p1.z, p1.w};
        int off[8];
        #pragma unroll
        for (int p = 0; p < 8; p++) off[p] = g_off[d[p]];
        #pragma unroll
        for (int p = 0; p < 8; p++) g_srcs[off[p] + pos[p]] = s[p];
        return;
    }

    // ---- GEMM path ----
    const int t    = threadIdx.x;
    const int lane = t & 31;
    const int w    = t >> 5;
    const int rowbase = blockIdx.x * GEMM_BM;

    for (int f4 = t; f4 < GEMM_BM * 32; f4 += 128) {
        const int row = f4 >> 5, c4 = f4 & 31;
        const int grow = rowbase + row;
        float4 v = make_float4(0.f, 0.f, 0.f, 0.f);
        if (grow < N_NODES) v = *(const float4*)(x + (size_t)grow * IN_F + c4 * 4);
        __half2 h0 = __floats2half2_rn(v.x, v.y);
        __half2 h1 = __floats2half2_rn(v.z, v.w);
        uint2 u;
        u.x = *(const unsigned*)&h0;
        u.y = *(const unsigned*)&h1;
        *(uint2*)&xh[row][c4 * 4] = u;
    }
    __syncthreads();

    float acc[16][4];
    #pragma unroll
    for (int n = 0; n < 16; n++)
        #pragma unroll
        for (int q = 0; q < 4; q++) acc[n][q] = 0.f;

    const int sr = w * 16 + (lane >> 2);
    const int cc = (lane & 3) * 2;

    #pragma unroll
    for (int ks = 0; ks < 8; ks++) {
        const int kb = ks * 16;
        const unsigned a0 = *(const unsigned*)&xh[sr][kb + cc];
        const unsigned a1 = *(const unsigned*)&xh[sr + 8][kb + cc];
        const unsigned a2 = *(const unsigned*)&xh[sr][kb + cc + 8];
        const unsigned a3 = *(const unsigned*)&xh[sr + 8][kb + cc + 8];
        #pragma unroll
        for (int j = 0; j < 8; j++) {
            const uint4 q = g_Wf[(ks * 8 + j) * 32 + lane];
            mma16816(acc[2 * j],     a0, a1, a2, a3, q.x, q.y);
            mma16816(acc[2 * j + 1], a0, a1, a2, a3, q.z, q.w);
        }
    }

    const int cq = lane & 3;
    const unsigned msk = 0xffffffffu;

    #pragma unroll
    for (int rh = 0; rh < 2; rh++) {
        const int row = rowbase + w * 16 + (lane >> 2) + rh * 8;
        const bool valid = (row < N_NODES);
        float ps[4] = {0.f, 0.f, 0.f, 0.f};
        float pd[4] = {0.f, 0.f, 0.f, 0.f};

        #pragma unroll
        for (int n = 0; n < 16; n++) {
            const float c0 = acc[n][rh * 2];
            const float c1 = acc[n][rh * 2 + 1];
            if (valid) {
                __half2 hp = __floats2half2_rn(c0, c1);
                ((unsigned*)g_h2)[(size_t)row * 64 + n * 4 + cq] = *(const unsigned*)&hp;
            }
            const int head = n >> 2;
            const int wc   = (n & 3) * 8 + cq * 2;
            const float2 asv = *(const float2*)&a[head * 64 + wc];
            const float2 adv = *(const float2*)&a[head * 64 + 32 + wc];
            ps[head] += c0 * asv.x + c1 * asv.y;
            pd[head] += c0 * adv.x + c1 * adv.y;
        }
        #pragma unroll
        for (int h = 0; h < 4; h++) {
            ps[h] += __shfl_xor_sync(msk, ps[h], 1);
            ps[h] += __shfl_xor_sync(msk, ps[h], 2);
            pd[h] += __shfl_xor_sync(msk, pd[h], 1);
            pd[h] += __shfl_xor_sync(msk, pd[h], 2);
        }
        if (valid) {
            g_as[row * HEADS + cq] = ps[cq];
            g_ad[row * HEADS + cq] = pd[cq];
        }
    }
}

// ---------------- gather: warp per node, half-warp per edge ---------------
__device__ __forceinline__ float leaky(float v) {
    return (v > 0.f) ? v : NEG_SLOPE * v;
}

__global__ __launch_bounds__(256) void gather_kernel(float* __restrict__ out) {
    const int n = blockIdx.x * 8 + (threadIdx.x >> 5);
    if (n >= N_NODES) return;
    const int lane = threadIdx.x & 31;
    const int hw = lane >> 4;
    const int sl = lane & 15;
    const int h  = sl >> 2;
    const float myad = g_ad[n * HEADS + h];

    float acc[8];
    #pragma unroll
    for (int j = 0; j < 8; j++) acc[j] = 0.f;

    const int start = g_off[n];
    const int end   = g_off[n + 1];
    int e = start;

    #pragma unroll 1
    for (; e + 8 <= end; e += 8) {
        int   si[4];
        uint4 u[4];
        float att[4];
        #pragma unroll
        for (int p = 0; p < 4; p++) si[p] = g_srcs[e + 2 * p + hw];
        #pragma unroll
        for (int p = 0; p < 4; p++) u[p] = *(const uint4*)&g_h2[(size_t)si[p] * 64 + sl * 4];
        #pragma unroll
        for (int p = 0; p < 4; p++) att[p] = leaky(g_as[si[p] * HEADS + h] + myad);
        #pragma unroll
        for (int p = 0; p < 4; p++) {
            float2 f;
            f = __half22float2(*(const __half2*)&u[p].x);
            acc[0] = fmaf(att[p], f.x, acc[0]); acc[1] = fmaf(att[p], f.y, acc[1]);
            f = __half22float2(*(const __half2*)&u[p].y);
            acc[2] = fmaf(att[p], f.x, acc[2]); acc[3] = fmaf(att[p], f.y, acc[3]);
            f = __half22float2(*(const __half2*)&u[p].z);
            acc[4] = fmaf(att[p], f.x, acc[4]); acc[5] = fmaf(att[p], f.y, acc[5]);
            f = __half22float2(*(const __half2*)&u[p].w);
            acc[6] = fmaf(att[p], f.x, acc[6]); acc[7] = fmaf(att[p], f.y, acc[7]);
        }
    }
    #pragma unroll 1
    for (; e < end; e += 2) {
        if (e + hw < end) {
            const int s = g_srcs[e + hw];
            const float att = leaky(g_as[s * HEADS + h] + myad);
            const uint4 u = *(const uint4*)&g_h2[(size_t)s * 64 + sl * 4];
            float2 f;
            f = __half22float2(*(const __half2*)&u.x);
            acc[0] = fmaf(att, f.x, acc[0]); acc[1] = fmaf(att, f.y, acc[1]);
            f = __half22float2(*(const __half2*)&u.y);
            acc[2] = fmaf(att, f.x, acc[2]); acc[3] = fmaf(att, f.y, acc[3]);
            f = __half22float2(*(const __half2*)&u.z);
            acc[4] = fmaf(att, f.x, acc[4]); acc[5] = fmaf(att, f.y, acc[5]);
            f = __half22float2(*(const __half2*)&u.w);
            acc[6] = fmaf(att, f.x, acc[6]); acc[7] = fmaf(att, f.y, acc[7]);
        }
    }

    const unsigned msk = 0xffffffffu;
    #pragma unroll
    for (int j = 0; j < 8; j++)
        acc[j] += __shfl_xor_sync(msk, acc[j], 16);

    float* op = out + (size_t)n * OUT_F + sl * 8;
    if (hw == 0)
        *(float4*)op = make_float4(acc[0], acc[1], acc[2], acc[3]);
    else
        *(float4*)(op + 4) = make_float4(acc[4], acc[5], acc[6], acc[7]);
}

// ---------------- launch: single linear graph ------------------------------
extern "C" void kernel_launch(void* const* d_in, const int* in_sizes, int n_in,
                              void* d_out, int out_size) {
    const float* x  = (const float*)d_in[0];
    const int*   ei = (const int*)d_in[1];
    const float* W  = (const float*)d_in[2];
    const float* a  = (const float*)d_in[3];
    float* out = (float*)d_out;

    void* cntp = nullptr;
    cudaGetSymbolAddress(&cntp, g_cnt);

    detect_kernel<<<1, 1>>>(ei);
    cudaMemsetAsync(cntp, 0, N_NODES * sizeof(int));
    init_kernel<<<8, 256>>>(W);
    hist_kernel<<<HIST_BLOCKS, 256>>>(ei);
    scan_kernel<<<1, 1024>>>();
    gemm_scatter_kernel<<<GEMM_BLOCKS + SCAT_BLOCKS, 128>>>(x, ei, a);
    gather_kernel<<<(N_NODES + 7) / 8, 256>>>(out);
}

// round 16
// speedup vs baseline: 1.3676x; 1.0786x over previous
#include <cuda_runtime.h>
#include <cuda_fp16.h>
#include <stdint.h>

#define N_NODES  50000
#define N_EDGES  1600000
#define IN_F     128
#define OUT_F    128
#define HEADS    4
#define HEAD_DIM 32
#define NEG_SLOPE 0.2f

#define GEMM_BM      64
#define GEMM_BLOCKS  782            // ceil(50000/64)
#define HIST_BLOCKS  3125           // 1.6M / (128 thr * 4 edges)
#define SCAT_BLOCKS  782            // ceil(1.6M / (256 thr * 8 edges))
#define SCAN_BLOCKS  196            // ceil(50000/256)

// ---------------- device scratch ----------------
__device__ __half2 g_h2[N_NODES * (OUT_F / 2)];  // h as half2 (12.8 MB)
__device__ float   g_as[N_NODES * HEADS];
__device__ float   g_ad[N_NODES * HEADS];
__device__ uint4   g_Wf[2048];                   // W in mma B-fragment layout (32KB)
__device__ int     g_cnt[N_NODES];
__device__ int     g_off[N_NODES + 1];
__device__ int     g_part[256];                  // per-block partial sums
__device__ int     g_pbase[256];                 // scanned partials (exclusive)
__device__ int     g_epos[N_EDGES];              // within-bucket position per edge
__device__ int     g_srcs[N_EDGES];              // src index, sorted by dst
__device__ int     g_is64;

// ---------------- dtype detect --------------------------------------------
__global__ void detect_kernel(const int* __restrict__ ei) {
    int allzero = 1;
    #pragma unroll 1
    for (int i2 = 1; i2 < 256; i2 += 2)
        if (ei[i2] != 0) { allzero = 0; break; }
    g_is64 = allzero;
}

// ---------------- W fragment packing ---------------------------------------
__global__ __launch_bounds__(256) void init_kernel(const float* __restrict__ W) {
    const int L = blockIdx.x * 256 + threadIdx.x;   // 8 blocks * 256 = 2048
    const int lane = L & 31;
    const int j    = (L >> 5) & 7;
    const int ks   = L >> 8;
    const int k0   = ks * 16 + (lane & 3) * 2;

    uint4 q;
    #pragma unroll
    for (int p = 0; p < 2; p++) {
        const int col = (2 * j + p) * 8 + (lane >> 2);
        const float* wr = W + col * IN_F;
        __half2 b0 = __floats2half2_rn(wr[k0],     wr[k0 + 1]);
        __half2 b1 = __floats2half2_rn(wr[k0 + 8], wr[k0 + 9]);
        if (p == 0) { q.x = *(const unsigned*)&b0; q.y = *(const unsigned*)&b1; }
        else        { q.z = *(const unsigned*)&b0; q.w = *(const unsigned*)&b1; }
    }
    g_Wf[L] = q;
}

// ---------------- fused tensor-core GEMM || hist+epos ----------------------
__device__ __forceinline__ void mma16816(
    float* c, unsigned a0, unsigned a1, unsigned a2, unsigned a3,
    unsigned b0, unsigned b1)
{
    asm volatile(
        "mma.sync.aligned.m16n8k16.row.col.f32.f16.f16.f32 "
        "{%0,%1,%2,%3}, {%4,%5,%6,%7}, {%8,%9}, {%0,%1,%2,%3};"
        : "+f"(c[0]), "+f"(c[1]), "+f"(c[2]), "+f"(c[3])
        : "r"(a0), "r"(a1), "r"(a2), "r"(a3), "r"(b0), "r"(b1));
}

__global__ __launch_bounds__(128) void gemm_hist_kernel(
    const float* __restrict__ x,
    const int*   __restrict__ ei32,
    const float* __restrict__ a)
{
    __shared__ __half xh[GEMM_BM][IN_F + 8];

    if (blockIdx.x >= GEMM_BLOCKS) {
        // ---- hist path: 4 edges/thread, returning atomics + epos ----
        const int e4 = (blockIdx.x - GEMM_BLOCKS) * 512 + threadIdx.x * 4;
        int d0, d1, d2, d3;
        if (g_is64) {
            const longlong2* p = (const longlong2*)((const long long*)ei32 + N_EDGES + e4);
            longlong2 va = p[0], vb = p[1];
            d0 = (int)va.x; d1 = (int)va.y; d2 = (int)vb.x; d3 = (int)vb.y;
        } else {
            int4 d = *(const int4*)(ei32 + N_EDGES + e4);
            d0 = d.x; d1 = d.y; d2 = d.z; d3 = d.w;
        }
        int p0 = atomicAdd(&g_cnt[d0], 1);
        int p1 = atomicAdd(&g_cnt[d1], 1);
        int p2 = atomicAdd(&g_cnt[d2], 1);
        int p3 = atomicAdd(&g_cnt[d3], 1);
        *(int4*)&g_epos[e4] = make_int4(p0, p1, p2, p3);
        return;
    }

    // ---- GEMM path ----
    const int t    = threadIdx.x;
    const int lane = t & 31;
    const int w    = t >> 5;
    const int rowbase = blockIdx.x * GEMM_BM;

    for (int f4 = t; f4 < GEMM_BM * 32; f4 += 128) {
        const int row = f4 >> 5, c4 = f4 & 31;
        const int grow = rowbase + row;
        float4 v = make_float4(0.f, 0.f, 0.f, 0.f);
        if (grow < N_NODES) v = *(const float4*)(x + (size_t)grow * IN_F + c4 * 4);
        __half2 h0 = __floats2half2_rn(v.x, v.y);
        __half2 h1 = __floats2half2_rn(v.z, v.w);
        uint2 u;
        u.x = *(const unsigned*)&h0;
        u.y = *(const unsigned*)&h1;
        *(uint2*)&xh[row][c4 * 4] = u;
    }
    __syncthreads();

    float acc[16][4];
    #pragma unroll
    for (int n = 0; n < 16; n++)
        #pragma unroll
        for (int q = 0; q < 4; q++) acc[n][q] = 0.f;

    const int sr = w * 16 + (lane >> 2);
    const int cc = (lane & 3) * 2;

    #pragma unroll
    for (int ks = 0; ks < 8; ks++) {
        const int kb = ks * 16;
        const unsigned a0 = *(const unsigned*)&xh[sr][kb + cc];
        const unsigned a1 = *(const unsigned*)&xh[sr + 8][kb + cc];
        const unsigned a2 = *(const unsigned*)&xh[sr][kb + cc + 8];
        const unsigned a3 = *(const unsigned*)&xh[sr + 8][kb + cc + 8];
        #pragma unroll
        for (int j = 0; j < 8; j++) {
            const uint4 q = g_Wf[(ks * 8 + j) * 32 + lane];
            mma16816(acc[2 * j],     a0, a1, a2, a3, q.x, q.y);
            mma16816(acc[2 * j + 1], a0, a1, a2, a3, q.z, q.w);
        }
    }

    const int cq = lane & 3;
    const unsigned msk = 0xffffffffu;

    #pragma unroll
    for (int rh = 0; rh < 2; rh++) {
        const int row = rowbase + w * 16 + (lane >> 2) + rh * 8;
        const bool valid = (row < N_NODES);
        float ps[4] = {0.f, 0.f, 0.f, 0.f};
        float pd[4] = {0.f, 0.f, 0.f, 0.f};

        #pragma unroll
        for (int n = 0; n < 16; n++) {
            const float c0 = acc[n][rh * 2];
            const float c1 = acc[n][rh * 2 + 1];
            if (valid) {
                __half2 hp = __floats2half2_rn(c0, c1);
                ((unsigned*)g_h2)[(size_t)row * 64 + n * 4 + cq] = *(const unsigned*)&hp;
            }
            const int head = n >> 2;
            const int wc   = (n & 3) * 8 + cq * 2;
            const float2 asv = *(const float2*)&a[head * 64 + wc];
            const float2 adv = *(const float2*)&a[head * 64 + 32 + wc];
            ps[head] += c0 * asv.x + c1 * asv.y;
            pd[head] += c0 * adv.x + c1 * adv.y;
        }
        #pragma unroll
        for (int h = 0; h < 4; h++) {
            ps[h] += __shfl_xor_sync(msk, ps[h], 1);
            ps[h] += __shfl_xor_sync(msk, ps[h], 2);
            pd[h] += __shfl_xor_sync(msk, pd[h], 1);
            pd[h] += __shfl_xor_sync(msk, pd[h], 2);
        }
        if (valid) {
            g_as[row * HEADS + cq] = ps[cq];
            g_ad[row * HEADS + cq] = pd[cq];
        }
    }
}

// ---------------- 3-phase multi-block scan --------------------------------
// All sub-warp stages run on ALL 32 lanes of warp 0 (inactive lanes carry 0);
// never a shuffle under a divergent guard.

// Phase 1: per-block sums of 256 counts
__global__ __launch_bounds__(256) void scan_part_kernel() {
    __shared__ int wsum[8];
    const int t = threadIdx.x;
    const int lane = t & 31, wid = t >> 5;
    const int idx = blockIdx.x * 256 + t;
    int v = (idx < N_NODES) ? g_cnt[idx] : 0;
    const unsigned m = 0xffffffffu;
    int s = v;
    #pragma unroll
    for (int off = 16; off > 0; off >>= 1) s += __shfl_xor_sync(m, s, off);
    if (lane == 0) wsum[wid] = s;
    __syncthreads();
    if (wid == 0) {
        int ws = (lane < 8) ? wsum[lane] : 0;
        #pragma unroll
        for (int off = 16; off > 0; off >>= 1) ws += __shfl_xor_sync(m, ws, off);
        if (lane == 0) g_part[blockIdx.x] = ws;
    }
}

// Phase 2: scan the 196 partials (1 block)
__global__ __launch_bounds__(256) void scan_base_kernel() {
    __shared__ int wtot[8];
    const int t = threadIdx.x;
    const int lane = t & 31, wid = t >> 5;
    const unsigned m = 0xffffffffu;
    int v = (t < SCAN_BLOCKS) ? g_part[t] : 0;
    int incl = v;
    #pragma unroll
    for (int off = 1; off < 32; off <<= 1) {
        int u = __shfl_up_sync(m, incl, off);
        if (lane >= off) incl += u;
    }
    if (lane == 31) wtot[wid] = incl;
    __syncthreads();
    if (wid == 0) {
        int w2 = (lane < 8) ? wtot[lane] : 0;
        #pragma unroll
        for (int off = 1; off < 32; off <<= 1) {
            int u = __shfl_up_sync(m, w2, off);
            if (lane >= off) w2 += u;
        }
        if (lane < 8) wtot[lane] = w2;
    }
    __syncthreads();
    const int excl = incl - v + (wid ? wtot[wid - 1] : 0);
    if (t < SCAN_BLOCKS) g_pbase[t] = excl;
    if (t == SCAN_BLOCKS - 1) g_off[N_NODES] = excl + v;
}

// Phase 3: block-local exclusive scan + base -> g_off
__global__ __launch_bounds__(256) void scan_off_kernel() {
    __shared__ int wtot[8];
    const int t = threadIdx.x;
    const int lane = t & 31, wid = t >> 5;
    const unsigned m = 0xffffffffu;
    const int idx = blockIdx.x * 256 + t;
    int v = (idx < N_NODES) ? g_cnt[idx] : 0;
    int incl = v;
    #pragma unroll
    for (int off = 1; off < 32; off <<= 1) {
        int u = __shfl_up_sync(m, incl, off);
        if (lane >= off) incl += u;
    }
    if (lane == 31) wtot[wid] = incl;
    __syncthreads();
    if (wid == 0) {
        int w2 = (lane < 8) ? wtot[lane] : 0;
        #pragma unroll
        for (int off = 1; off < 32; off <<= 1) {
            int u = __shfl_up_sync(m, w2, off);
            if (lane >= off) w2 += u;
        }
        if (lane < 8) wtot[lane] = w2;
    }
    __syncthreads();
    const int excl = incl - v + (wid ? wtot[wid - 1] : 0) + g_pbase[blockIdx.x];
    if (idx < N_NODES) g_off[idx] = excl;
}

// ---------------- scatter: atomic-free, 8 edges/thread --------------------
__global__ __launch_bounds__(256) void scatter_kernel(const int* __restrict__ ei32) {
    const int e8 = (blockIdx.x * blockDim.x + threadIdx.x) * 8;
    if (e8 >= N_EDGES) return;
    int s[8], d[8];
    if (g_is64) {
        const long long* ei = (const long long*)ei32;
        const longlong2* sp = (const longlong2*)(ei + e8);
        const longlong2* dp = (const longlong2*)(ei + N_EDGES + e8);
        #pragma unroll
        for (int q = 0; q < 4; q++) {
            longlong2 sv = sp[q], dv = dp[q];
            s[2*q] = (int)sv.x; s[2*q+1] = (int)sv.y;
            d[2*q] = (int)dv.x; d[2*q+1] = (int)dv.y;
        }
    } else {
        int4 sv0 = *(const int4*)(ei32 + e8);
        int4 sv1 = *(const int4*)(ei32 + e8 + 4);
        int4 dv0 = *(const int4*)(ei32 + N_EDGES + e8);
        int4 dv1 = *(const int4*)(ei32 + N_EDGES + e8 + 4);
        s[0]=sv0.x; s[1]=sv0.y; s[2]=sv0.z; s[3]=sv0.w;
        s[4]=sv1.x; s[5]=sv1.y; s[6]=sv1.z; s[7]=sv1.w;
        d[0]=dv0.x; d[1]=dv0.y; d[2]=dv0.z; d[3]=dv0.w;
        d[4]=dv1.x; d[5]=dv1.y; d[6]=dv1.z; d[7]=dv1.w;
    }
    int4 p0 = *(const int4*)&g_epos[e8];
    int4 p1 = *(const int4*)&g_epos[e8 + 4];
    int pos[8] = {p0.x, p0.y, p0.z, p0.w, p1.x, p1.y, p1.z, p1.w};
    int off[8];
    #pragma unroll
    for (int p = 0; p < 8; p++) off[p] = g_off[d[p]];
    #pragma unroll
    for (int p = 0; p < 8; p++) g_srcs[off[p] + pos[p]] = s[p];
}

// ---------------- gather: warp per node, half-warp per edge ---------------
__device__ __forceinline__ float leaky(float v) {
    return (v > 0.f) ? v : NEG_SLOPE * v;
}

__global__ __launch_bounds__(256) void gather_kernel(float* __restrict__ out) {
    const int n = blockIdx.x * 8 + (threadIdx.x >> 5);
    if (n >= N_NODES) return;
    const int lane = threadIdx.x & 31;
    const int hw = lane >> 4;
    const int sl = lane & 15;
    const int h  = sl >> 2;
    const float myad = g_ad[n * HEADS + h];

    float acc[8];
    #pragma unroll
    for (int j = 0; j < 8; j++) acc[j] = 0.f;

    const int start = g_off[n];
    const int end   = g_off[n + 1];
    int e = start;

    #pragma unroll 1
    for (; e + 8 <= end; e += 8) {
        int   si[4];
        uint4 u[4];
        float att[4];
        #pragma unroll
        for (int p = 0; p < 4; p++) si[p] = g_srcs[e + 2 * p + hw];
        #pragma unroll
        for (int p = 0; p < 4; p++) u[p] = *(const uint4*)&g_h2[(size_t)si[p] * 64 + sl * 4];
        #pragma unroll
        for (int p = 0; p < 4; p++) att[p] = leaky(g_as[si[p] * HEADS + h] + myad);
        #pragma unroll
        for (int p = 0; p < 4; p++) {
            float2 f;
            f = __half22float2(*(const __half2*)&u[p].x);
            acc[0] = fmaf(att[p], f.x, acc[0]); acc[1] = fmaf(att[p], f.y, acc[1]);
            f = __half22float2(*(const __half2*)&u[p].y);
            acc[2] = fmaf(att[p], f.x, acc[2]); acc[3] = fmaf(att[p], f.y, acc[3]);
            f = __half22float2(*(const __half2*)&u[p].z);
            acc[4] = fmaf(att[p], f.x, acc[4]); acc[5] = fmaf(att[p], f.y, acc[5]);
            f = __half22float2(*(const __half2*)&u[p].w);
            acc[6] = fmaf(att[p], f.x, acc[6]); acc[7] = fmaf(att[p], f.y, acc[7]);
        }
    }
    #pragma unroll 1
    for (; e < end; e += 2) {
        if (e + hw < end) {
            const int s = g_srcs[e + hw];
            const float att = leaky(g_as[s * HEADS + h] + myad);
            const uint4 u = *(const uint4*)&g_h2[(size_t)s * 64 + sl * 4];
            float2 f;
            f = __half22float2(*(const __half2*)&u.x);
            acc[0] = fmaf(att, f.x, acc[0]); acc[1] = fmaf(att, f.y, acc[1]);
            f = __half22float2(*(const __half2*)&u.y);
            acc[2] = fmaf(att, f.x, acc[2]); acc[3] = fmaf(att, f.y, acc[3]);
            f = __half22float2(*(const __half2*)&u.z);
            acc[4] = fmaf(att, f.x, acc[4]); acc[5] = fmaf(att, f.y, acc[5]);
            f = __half22float2(*(const __half2*)&u.w);
            acc[6] = fmaf(att, f.x, acc[6]); acc[7] = fmaf(att, f.y, acc[7]);
        }
    }

    const unsigned msk = 0xffffffffu;
    #pragma unroll
    for (int j = 0; j < 8; j++)
        acc[j] += __shfl_xor_sync(msk, acc[j], 16);

    float* op = out + (size_t)n * OUT_F + sl * 8;
    if (hw == 0)
        *(float4*)op = make_float4(acc[0], acc[1], acc[2], acc[3]);
    else
        *(float4*)(op + 4) = make_float4(acc[4], acc[5], acc[6], acc[7]);
}

// ---------------- launch: single linear graph ------------------------------
extern "C" void kernel_launch(void* const* d_in, const int* in_sizes, int n_in,
                              void* d_out, int out_size) {
    const float* x  = (const float*)d_in[0];
    const int*   ei = (const int*)d_in[1];
    const float* W  = (const float*)d_in[2];
    const float* a  = (const float*)d_in[3];
    float* out = (float*)d_out;

    void* cntp = nullptr;
    cudaGetSymbolAddress(&cntp, g_cnt);

    detect_kernel<<<1, 1>>>(ei);
    cudaMemsetAsync(cntp, 0, N_NODES * sizeof(int));
    init_kernel<<<8, 256>>>(W);
    gemm_hist_kernel<<<GEMM_BLOCKS + HIST_BLOCKS, 128>>>(x, ei, a);
    scan_part_kernel<<<SCAN_BLOCKS, 256>>>();
    scan_base_kernel<<<1, 256>>>();
    scan_off_kernel<<<SCAN_BLOCKS, 256>>>();
    scatter_kernel<<<SCAT_BLOCKS, 256>>>(ei);
    gather_kernel<<<(N_NODES + 7) / 8, 256>>>(out);
}